// round 1
// baseline (speedup 1.0000x reference)
#include <cuda_runtime.h>
#include <math.h>

// ---------------------------------------------------------------------------
// MambaLayer_image: 3 stages of bidirectional selective scan over 24^3 voxels.
// L = 13824 sequence positions, C = 128 channels (split 64/64 fwd/bwd lanes).
// All activations kept as (S, C) row-major; permutations via index maps.
// ---------------------------------------------------------------------------

namespace {
constexpr int L    = 13824;   // D*H*W = 24^3
constexpr int C    = 128;
constexpr int DM   = 64;
constexpr int DI   = 128;
constexpr int DS   = 8;
constexpr int NCH  = 216;     // scan chunks
constexpr int CLEN = 64;      // chunk length (216*64 = 13824)
}

// ------------------------- device global scratch ---------------------------
__device__ __align__(16) float g_curA[L * C];
__device__ __align__(16) float g_curB[L * C];
__device__ __align__(16) float g_u[2][L * DM];
__device__ __align__(16) float g_xcp[2][L * DI];
__device__ __align__(16) float g_z[2][L * DI];
__device__ __align__(16) float g_xc[2][L * DI];
__device__ __align__(16) float g_dt[2][L * DI];
__device__ __align__(16) float g_bc[2][L * 16];
__device__ __align__(16) float g_yz[2][L * DI];
__device__ __align__(16) float g_ap[2][NCH * DI * DS];
__device__ __align__(16) float g_hl[2][NCH * DI * DS];
__device__ __align__(16) float g_hin[2][NCH * DI * DS];
__device__ __align__(16) float g_wTin[6 * DM * 256];   // [blk][d][e]
__device__ __align__(16) float g_wTout[6 * DI * DM];   // [blk][d][o]

__device__ __forceinline__ float* curbuf(int i) { return i ? g_curB : g_curA; }

// spatial index for flattened permuted order l -> canonical spatial index s
__device__ __forceinline__ int smap(int l, int mode) {
    if (mode == 0) return l;
    int a = l / 576;
    int r = l - a * 576;
    int b = r / 24;
    int c3 = r - b * 24;
    return (mode == 1) ? (c3 * 576 + a * 24 + b) : (b * 576 + c3 * 24 + a);
}

__device__ __forceinline__ float siluf(float x) {
    return x / (1.0f + __expf(-x));
}

// ------------------------- weight transposes -------------------------------
__global__ void k_wt(const float* __restrict__ inw, const float* __restrict__ opw) {
    int tid = blockIdx.x * 256 + threadIdx.x;
    if (tid < 6 * 256 * 64) {
        int b = tid / 16384;
        int r = tid - b * 16384;
        int e = r / 64;
        int d = r - e * 64;
        g_wTin[b * 16384 + d * 256 + e] = inw[tid];
    }
    if (tid < 6 * 64 * 128) {
        int b = tid / 8192;
        int r = tid - b * 8192;
        int o = r / 128;
        int d = r - o * 128;
        g_wTout[b * 8192 + d * 64 + o] = opw[tid];
    }
}

// ------------------------- input transpose (C,S) -> (S,C) ------------------
__global__ void k_tin(const float* __restrict__ x) {
    __shared__ float tile[32][33];
    int s0 = blockIdx.x * 32, c0 = blockIdx.y * 32;
    int tx = threadIdx.x, ty = threadIdx.y;
    tile[ty][tx] = x[(c0 + ty) * L + s0 + tx];
    __syncthreads();
    g_curA[(s0 + ty) * C + c0 + tx] = tile[tx][ty];
}

// ------------------------- final: out = cur^T + x --------------------------
__global__ void k_fin(const float* __restrict__ x, float* __restrict__ out) {
    __shared__ float tile[32][33];
    int s0 = blockIdx.x * 32, c0 = blockIdx.y * 32;
    int tx = threadIdx.x, ty = threadIdx.y;
    tile[ty][tx] = g_curB[(s0 + ty) * C + c0 + tx];
    __syncthreads();
    out[(c0 + ty) * L + s0 + tx] = tile[tx][ty] + x[(c0 + ty) * L + s0 + tx];
}

// ------------------------- layernorm + split + reverse ---------------------
__global__ void k_ln(int inb, const float* __restrict__ lg,
                     const float* __restrict__ lb, int mode) {
    int l = blockIdx.x;
    int c = threadIdx.x;
    const float* cur = curbuf(inb);
    int s = smap(l, mode);
    float v = cur[s * C + c];

    __shared__ float red[8];
    float sum = v, sq = v * v;
    #pragma unroll
    for (int o = 16; o > 0; o >>= 1) {
        sum += __shfl_xor_sync(0xffffffffu, sum, o);
        sq  += __shfl_xor_sync(0xffffffffu, sq,  o);
    }
    int w = c >> 5;
    if ((c & 31) == 0) { red[w] = sum; red[4 + w] = sq; }
    __syncthreads();
    float ts = red[0] + red[1] + red[2] + red[3];
    float tq = red[4] + red[5] + red[6] + red[7];
    float m   = ts * (1.0f / 128.0f);
    float var = tq * (1.0f / 128.0f) - m * m;
    float xn  = (v - m) * rsqrtf(var + 1e-5f) * lg[c] + lb[c];

    if (c < DM) g_u[0][l * DM + c] = xn;
    else        g_u[1][(L - 1 - l) * DM + (c - DM)] = xn;   // reversed lane
}

// ------------------------- in_proj GEMM (L,64)x(64,256) --------------------
__global__ void __launch_bounds__(256) k_inproj(int stage) {
    int lane = blockIdx.y;
    int blk  = 2 * stage + lane;
    const float4* wT = (const float4*)(g_wTin + blk * DM * 256);
    __shared__ float us[32][65];
    int tid = threadIdx.x;
    int l0 = blockIdx.x * 32;
    const float* u = g_u[lane];
    for (int k = tid; k < 32 * 64; k += 256) {
        int r = k >> 6, d = k & 63;
        us[r][d] = u[(l0 + r) * DM + d];
    }
    __syncthreads();

    int e4 = tid & 63;        // float4 column group: cols e4*4 .. e4*4+3
    int rg = tid >> 6;        // 0..3 -> 8 rows each
    int r0 = rg * 8;
    float acc[4][8];
    #pragma unroll
    for (int q = 0; q < 4; q++)
        #pragma unroll
        for (int r = 0; r < 8; r++) acc[q][r] = 0.0f;

    #pragma unroll 4
    for (int d = 0; d < 64; d++) {
        float4 w = wT[d * 64 + e4];
        #pragma unroll
        for (int r = 0; r < 8; r++) {
            float uv = us[r0 + r][d];
            acc[0][r] += w.x * uv;
            acc[1][r] += w.y * uv;
            acc[2][r] += w.z * uv;
            acc[3][r] += w.w * uv;
        }
    }
    int e0 = e4 * 4;
    float* dst;
    int off;
    if (e0 < 128) { dst = g_xcp[lane]; off = e0; }
    else          { dst = g_z[lane];   off = e0 - 128; }
    #pragma unroll
    for (int r = 0; r < 8; r++) {
        int l = l0 + r0 + r;
        float4 o = make_float4(acc[0][r], acc[1][r], acc[2][r], acc[3][r]);
        *(float4*)(dst + l * DI + off) = o;
    }
}

// ------------------------- causal depthwise conv + silu --------------------
__global__ void k_conv(int stage, const float* __restrict__ cw,
                       const float* __restrict__ cb) {
    int lane = blockIdx.y;
    int blk  = 2 * stage + lane;
    int idx = blockIdx.x * 256 + threadIdx.x;    // < L*DI
    int l = idx >> 7;
    int d = idx & 127;
    const float* xp = g_xcp[lane];
    float4 w = *(const float4*)(cw + (blk * DI + d) * 4);
    float b = cb[blk * DI + d];
    float s = w.w * xp[l * DI + d];
    if (l >= 1) s += w.z * xp[(l - 1) * DI + d];
    if (l >= 2) s += w.y * xp[(l - 2) * DI + d];
    if (l >= 3) s += w.x * xp[(l - 3) * DI + d];
    s += b;
    g_xc[lane][idx] = siluf(s);
}

// ------------------------- x_proj + dt_proj (warp per row) -----------------
__global__ void k_xdt(int stage, const float* __restrict__ xpw,
                      const float* __restrict__ dpw,
                      const float* __restrict__ dpb) {
    int lane = blockIdx.y;
    int blk  = 2 * stage + lane;
    int wid = threadIdx.x >> 5;
    int t   = threadIdx.x & 31;
    int l = blockIdx.x * 4 + wid;

    const float4* xc4 = (const float4*)(g_xc[lane] + l * DI);
    float4 xv = xc4[t];
    const float4* w4 = (const float4*)(xpw + blk * 20 * DI);

    float db0 = 0, db1 = 0, db2 = 0, db3 = 0, bcv = 0;
    #pragma unroll
    for (int e = 0; e < 20; e++) {
        float4 w = w4[e * 32 + t];
        float p = xv.x * w.x + xv.y * w.y + xv.z * w.z + xv.w * w.w;
        #pragma unroll
        for (int o = 16; o > 0; o >>= 1)
            p += __shfl_xor_sync(0xffffffffu, p, o);
        if (e == 0) db0 = p;
        else if (e == 1) db1 = p;
        else if (e == 2) db2 = p;
        else if (e == 3) db3 = p;
        else { if (t == e - 4) bcv = p; }
    }

    const float4* dp4 = (const float4*)(dpw + blk * DI * 4);
    #pragma unroll
    for (int j = 0; j < 4; j++) {
        int d = j * 32 + t;
        float4 w = dp4[d];
        float x = db0 * w.x + db1 * w.y + db2 * w.z + db3 * w.w + dpb[blk * DI + d];
        // stable softplus
        float sp = fmaxf(x, 0.0f) + log1pf(__expf(-fabsf(x)));
        g_dt[lane][l * DI + d] = sp;
    }
    if (t < 16) g_bc[lane][l * 16 + t] = bcv;
}

// ------------------------- scan phase 1: per-chunk local scan --------------
__global__ void __launch_bounds__(128) k_scan1(int stage, const float* __restrict__ alog) {
    int lane = blockIdx.y;
    int blk  = 2 * stage + lane;
    int ch = blockIdx.x;
    int d  = threadIdx.x;
    int l0 = ch * CLEN;

    float a[DS];
    #pragma unroll
    for (int s = 0; s < DS; s++)
        a[s] = -__expf(alog[(blk * DI + d) * DS + s]);

    __shared__ float Bs[CLEN][DS];
    for (int k = d; k < CLEN * DS; k += 128) {
        int r = k >> 3, s = k & 7;
        Bs[r][s] = g_bc[lane][(l0 + r) * 16 + s];
    }
    __syncthreads();

    float h[DS], ap[DS];
    #pragma unroll
    for (int s = 0; s < DS; s++) { h[s] = 0.0f; ap[s] = 1.0f; }

    const float* dt = g_dt[lane];
    const float* xc = g_xc[lane];
    int base = l0 * DI + d;
    float dtv = dt[base], xcv = xc[base];
    for (int i = 0; i < CLEN; i++) {
        float dtn = 0.0f, xcn = 0.0f;
        if (i + 1 < CLEN) {
            dtn = dt[base + (i + 1) * DI];
            xcn = xc[base + (i + 1) * DI];
        }
        float w = dtv * xcv;
        #pragma unroll
        for (int s = 0; s < DS; s++) {
            float dA = __expf(dtv * a[s]);
            h[s]  = dA * h[s] + w * Bs[i][s];
            ap[s] *= dA;
        }
        dtv = dtn; xcv = xcn;
    }
    float* apd = g_ap[lane] + ch * (DI * DS) + d * DS;
    float* hld = g_hl[lane] + ch * (DI * DS) + d * DS;
    *(float4*)(apd)     = make_float4(ap[0], ap[1], ap[2], ap[3]);
    *(float4*)(apd + 4) = make_float4(ap[4], ap[5], ap[6], ap[7]);
    *(float4*)(hld)     = make_float4(h[0], h[1], h[2], h[3]);
    *(float4*)(hld + 4) = make_float4(h[4], h[5], h[6], h[7]);
}

// ------------------------- scan phase 2: chunk combine ---------------------
__global__ void k_scan2() {
    int lane = blockIdx.x;
    int tid = threadIdx.x;
    float h = 0.0f;
    for (int ch = 0; ch < NCH; ch++) {
        int base = ch * (DI * DS) + tid;
        g_hin[lane][base] = h;
        h = g_ap[lane][base] * h + g_hl[lane][base];
    }
}

// ------------------------- scan phase 3: replay + output -------------------
__global__ void __launch_bounds__(128) k_scan3(int stage, const float* __restrict__ alog,
                                               const float* __restrict__ Dp) {
    int lane = blockIdx.y;
    int blk  = 2 * stage + lane;
    int ch = blockIdx.x;
    int d  = threadIdx.x;
    int l0 = ch * CLEN;

    float a[DS];
    #pragma unroll
    for (int s = 0; s < DS; s++)
        a[s] = -__expf(alog[(blk * DI + d) * DS + s]);
    float dpar = Dp[blk * DI + d];

    __shared__ float Bs[CLEN][DS];
    __shared__ float Cs[CLEN][DS];
    for (int k = d; k < CLEN * DS; k += 128) {
        int r = k >> 3, s = k & 7;
        Bs[r][s] = g_bc[lane][(l0 + r) * 16 + s];
        Cs[r][s] = g_bc[lane][(l0 + r) * 16 + 8 + s];
    }
    __syncthreads();

    float h[DS];
    const float* hind = g_hin[lane] + ch * (DI * DS) + d * DS;
    float4 h03 = *(const float4*)(hind);
    float4 h47 = *(const float4*)(hind + 4);
    h[0] = h03.x; h[1] = h03.y; h[2] = h03.z; h[3] = h03.w;
    h[4] = h47.x; h[5] = h47.y; h[6] = h47.z; h[7] = h47.w;

    const float* dt = g_dt[lane];
    const float* xc = g_xc[lane];
    const float* zz = g_z[lane];
    float* yz = g_yz[lane];
    int base = l0 * DI + d;
    float dtv = dt[base], xcv = xc[base], zv = zz[base];
    for (int i = 0; i < CLEN; i++) {
        float dtn = 0.0f, xcn = 0.0f, zn = 0.0f;
        if (i + 1 < CLEN) {
            dtn = dt[base + (i + 1) * DI];
            xcn = xc[base + (i + 1) * DI];
            zn  = zz[base + (i + 1) * DI];
        }
        float w = dtv * xcv;
        float y = dpar * xcv;
        #pragma unroll
        for (int s = 0; s < DS; s++) {
            float dA = __expf(dtv * a[s]);
            h[s] = dA * h[s] + w * Bs[i][s];
            y += h[s] * Cs[i][s];
        }
        yz[base + i * DI] = y * siluf(zv);
        dtv = dtn; xcv = xcn; zv = zn;
    }
}

// ------------------------- out_proj GEMM + residual + scatter --------------
__global__ void __launch_bounds__(256) k_outproj(int stage, int inb, int outb, int mode) {
    int lane = blockIdx.y;
    int blk  = 2 * stage + lane;
    __shared__ float ys[32][129];
    int tid = threadIdx.x;
    int l0 = blockIdx.x * 32;
    const float* yz = g_yz[lane];
    for (int k = tid; k < 32 * 128; k += 256) {
        int r = k >> 7, d = k & 127;
        ys[r][d] = yz[(l0 + r) * DI + d];
    }
    __syncthreads();

    int og = tid & 15;        // cols og*4 .. og*4+3 (of 64)
    int rg = tid >> 4;        // 0..15 -> 2 rows each
    int r0 = rg * 2;
    const float4* wT = (const float4*)(g_wTout + blk * DI * DM);

    float acc[4][2];
    #pragma unroll
    for (int q = 0; q < 4; q++) { acc[q][0] = 0.0f; acc[q][1] = 0.0f; }

    #pragma unroll 4
    for (int d = 0; d < 128; d++) {
        float4 w = wT[d * 16 + og];
        float y0 = ys[r0][d];
        float y1 = ys[r0 + 1][d];
        acc[0][0] += w.x * y0;  acc[0][1] += w.x * y1;
        acc[1][0] += w.y * y0;  acc[1][1] += w.y * y1;
        acc[2][0] += w.z * y0;  acc[2][1] += w.z * y1;
        acc[3][0] += w.w * y0;  acc[3][1] += w.w * y1;
    }

    const float* curIn = curbuf(inb);
    float* curOut = curbuf(outb);
    int o0 = og * 4;
    #pragma unroll
    for (int rr = 0; rr < 2; rr++) {
        int l = l0 + r0 + rr;
        int lt = lane ? (L - 1 - l) : l;   // undo sequence reversal for bwd lane
        int s = smap(lt, mode);
        int cc = lane * 64 + o0;
        float4 ri = *(const float4*)(curIn + s * C + cc);
        float4 ov;
        ov.x = acc[0][rr] + ri.x;
        ov.y = acc[1][rr] + ri.y;
        ov.z = acc[2][rr] + ri.z;
        ov.w = acc[3][rr] + ri.w;
        *(float4*)(curOut + s * C + cc) = ov;
    }
}

// ---------------------------------------------------------------------------
extern "C" void kernel_launch(void* const* d_in, const int* in_sizes, int n_in,
                              void* d_out, int out_size) {
    (void)in_sizes; (void)n_in; (void)out_size;
    const float* x    = (const float*)d_in[0];
    const float* inw  = (const float*)d_in[1];
    const float* cw   = (const float*)d_in[2];
    const float* cb   = (const float*)d_in[3];
    const float* xpw  = (const float*)d_in[4];
    const float* dpw  = (const float*)d_in[5];
    const float* dpb  = (const float*)d_in[6];
    const float* alog = (const float*)d_in[7];
    const float* Dp   = (const float*)d_in[8];
    const float* opw  = (const float*)d_in[9];
    const float* lg   = (const float*)d_in[10];
    const float* lb   = (const float*)d_in[11];
    float* out = (float*)d_out;

    k_wt<<<384, 256>>>(inw, opw);
    k_tin<<<dim3(L / 32, C / 32), dim3(32, 32)>>>(x);

    for (int st = 0; st < 3; st++) {
        int inb  = (st == 1) ? 1 : 0;
        int outb = 1 - inb;
        int mode = st;
        k_ln<<<L, 128>>>(inb, lg + st * C, lb + st * C, mode);
        k_inproj<<<dim3(L / 32, 2), 256>>>(st);
        k_conv<<<dim3(L * DI / 256, 2), 256>>>(st, cw, cb);
        k_xdt<<<dim3(L / 4, 2), 128>>>(st, xpw, dpw, dpb);
        k_scan1<<<dim3(NCH, 2), 128>>>(st, alog);
        k_scan2<<<2, 1024>>>();
        k_scan3<<<dim3(NCH, 2), 128>>>(st, alog, Dp);
        k_outproj<<<dim3(L / 32, 2), 256>>>(st, inb, outb, mode);
    }

    k_fin<<<dim3(L / 32, C / 32), dim3(32, 32)>>>(x, out);
}

// round 2
// speedup vs baseline: 1.3041x; 1.3041x over previous
#include <cuda_runtime.h>
#include <math.h>

// ---------------------------------------------------------------------------
// MambaLayer_image: 3 stages of bidirectional selective scan over 24^3 voxels.
// ---------------------------------------------------------------------------

namespace {
constexpr int L    = 13824;   // 24^3
constexpr int C    = 128;
constexpr int DM   = 64;
constexpr int DI   = 128;
constexpr int DS   = 8;
constexpr int CLEN = 32;      // scan chunk length
constexpr int NCH  = L / CLEN; // 432
}

// ------------------------- device global scratch ---------------------------
__device__ __align__(16) float g_curA[L * C];
__device__ __align__(16) float g_curB[L * C];
__device__ __align__(16) float g_u[2][L * DM];
__device__ __align__(16) float g_xcp[2][L * DI];
__device__ __align__(16) float g_z[2][L * DI];
__device__ __align__(16) float g_xc[2][L * DI];
__device__ __align__(16) float g_dt[2][L * DI];
__device__ __align__(16) float g_bc[2][L * 16];
__device__ __align__(16) float g_yz[2][L * DI];
__device__ __align__(16) float2 g_aphl[2][NCH * DI * DS];
__device__ __align__(16) float g_hin[2][NCH * DI * DS];
__device__ __align__(16) float g_wTin[6 * DM * 256];   // [blk][d][e]
__device__ __align__(16) float g_wTout[6 * DI * DM];   // [blk][d][o]

__device__ __forceinline__ float* curbuf(int i) { return i ? g_curB : g_curA; }

__device__ __forceinline__ int smap(int l, int mode) {
    if (mode == 0) return l;
    int a = l / 576;
    int r = l - a * 576;
    int b = r / 24;
    int c3 = r - b * 24;
    return (mode == 1) ? (c3 * 576 + a * 24 + b) : (b * 576 + c3 * 24 + a);
}

__device__ __forceinline__ float siluf(float x) {
    return x / (1.0f + __expf(-x));
}

// ---- packed f32x2 helpers (FFMA2 path: ptxas won't emit this from C++) ----
__device__ __forceinline__ unsigned long long pk2(float lo, float hi) {
    unsigned long long r;
    asm("mov.b64 %0, {%1, %2};" : "=l"(r)
        : "r"(__float_as_uint(lo)), "r"(__float_as_uint(hi)));
    return r;
}
__device__ __forceinline__ void upk2(unsigned long long v, float& lo, float& hi) {
    unsigned int a, b;
    asm("mov.b64 {%0, %1}, %2;" : "=r"(a), "=r"(b) : "l"(v));
    lo = __uint_as_float(a); hi = __uint_as_float(b);
}
__device__ __forceinline__ void fma2(unsigned long long& d,
                                     unsigned long long a, unsigned long long b) {
    asm("fma.rn.f32x2 %0, %1, %2, %0;" : "+l"(d) : "l"(a), "l"(b));
}

// ------------------------- weight transposes -------------------------------
__global__ void k_wt(const float* __restrict__ inw, const float* __restrict__ opw) {
    int tid = blockIdx.x * 256 + threadIdx.x;
    if (tid < 6 * 256 * 64) {
        int b = tid / 16384;
        int r = tid - b * 16384;
        int e = r / 64;
        int d = r - e * 64;
        g_wTin[b * 16384 + d * 256 + e] = inw[tid];
    }
    if (tid < 6 * 64 * 128) {
        int b = tid / 8192;
        int r = tid - b * 8192;
        int o = r / 128;
        int d = r - o * 128;
        g_wTout[b * 8192 + d * 64 + o] = opw[tid];
    }
}

// ------------------------- input transpose (C,S) -> (S,C) ------------------
__global__ void k_tin(const float* __restrict__ x) {
    __shared__ float tile[32][33];
    int s0 = blockIdx.x * 32, c0 = blockIdx.y * 32;
    int tx = threadIdx.x, ty = threadIdx.y;
    tile[ty][tx] = x[(c0 + ty) * L + s0 + tx];
    __syncthreads();
    g_curA[(s0 + ty) * C + c0 + tx] = tile[tx][ty];
}

// ------------------------- final: out = cur^T + x --------------------------
__global__ void k_fin(const float* __restrict__ x, float* __restrict__ out) {
    __shared__ float tile[32][33];
    int s0 = blockIdx.x * 32, c0 = blockIdx.y * 32;
    int tx = threadIdx.x, ty = threadIdx.y;
    tile[ty][tx] = g_curB[(s0 + ty) * C + c0 + tx];
    __syncthreads();
    out[(c0 + ty) * L + s0 + tx] = tile[tx][ty] + x[(c0 + ty) * L + s0 + tx];
}

// ------------------------- layernorm + split + reverse ---------------------
__global__ void k_ln(int inb, const float* __restrict__ lg,
                     const float* __restrict__ lb, int mode) {
    int l = blockIdx.x;
    int c = threadIdx.x;
    const float* cur = curbuf(inb);
    int s = smap(l, mode);
    float v = cur[s * C + c];

    __shared__ float red[8];
    float sum = v, sq = v * v;
    #pragma unroll
    for (int o = 16; o > 0; o >>= 1) {
        sum += __shfl_xor_sync(0xffffffffu, sum, o);
        sq  += __shfl_xor_sync(0xffffffffu, sq,  o);
    }
    int w = c >> 5;
    if ((c & 31) == 0) { red[w] = sum; red[4 + w] = sq; }
    __syncthreads();
    float ts = red[0] + red[1] + red[2] + red[3];
    float tq = red[4] + red[5] + red[6] + red[7];
    float m   = ts * (1.0f / 128.0f);
    float var = tq * (1.0f / 128.0f) - m * m;
    float xn  = (v - m) * rsqrtf(var + 1e-5f) * lg[c] + lb[c];

    if (c < DM) g_u[0][l * DM + c] = xn;
    else        g_u[1][(L - 1 - l) * DM + (c - DM)] = xn;
}

// ------------------------- in_proj GEMM (L,64)x(64,256), FFMA2 -------------
__global__ void __launch_bounds__(256) k_inproj(int stage) {
    int lane = blockIdx.y;
    int blk  = 2 * stage + lane;
    const float4* wT = (const float4*)(g_wTin + blk * DM * 256);
    __shared__ float us_t[64][34];   // [d][r], even stride for LDS.64
    int tid = threadIdx.x;
    int l0 = blockIdx.x * 32;
    const float* u = g_u[lane];
    for (int k = tid; k < 2048; k += 256) {
        int r = k >> 6, d = k & 63;
        us_t[d][r] = u[(l0 + r) * DM + d];
    }
    __syncthreads();

    int e4 = tid & 63;        // float4 column group
    int rg = tid >> 6;        // 4 groups of 8 rows
    int r0 = rg * 8;
    unsigned long long acc[4][4];   // [col q][row-pair p]
    #pragma unroll
    for (int q = 0; q < 4; q++)
        #pragma unroll
        for (int p = 0; p < 4; p++) acc[q][p] = 0ULL;

    #pragma unroll 4
    for (int d = 0; d < 64; d++) {
        float4 w = wT[d * 64 + e4];
        unsigned long long wx = pk2(w.x, w.x);
        unsigned long long wy = pk2(w.y, w.y);
        unsigned long long wz = pk2(w.z, w.z);
        unsigned long long ww = pk2(w.w, w.w);
        #pragma unroll
        for (int p = 0; p < 4; p++) {
            unsigned long long up = *(const unsigned long long*)&us_t[d][r0 + 2 * p];
            fma2(acc[0][p], wx, up);
            fma2(acc[1][p], wy, up);
            fma2(acc[2][p], wz, up);
            fma2(acc[3][p], ww, up);
        }
    }
    int e0 = e4 * 4;
    float* dst;
    int off;
    if (e0 < 128) { dst = g_xcp[lane]; off = e0; }
    else          { dst = g_z[lane];   off = e0 - 128; }
    #pragma unroll
    for (int p = 0; p < 4; p++) {
        float x0, x1, y0, y1, z0, z1, w0, w1;
        upk2(acc[0][p], x0, x1);
        upk2(acc[1][p], y0, y1);
        upk2(acc[2][p], z0, z1);
        upk2(acc[3][p], w0, w1);
        int l = l0 + r0 + 2 * p;
        *(float4*)(dst + l * DI + off)       = make_float4(x0, y0, z0, w0);
        *(float4*)(dst + (l + 1) * DI + off) = make_float4(x1, y1, z1, w1);
    }
}

// --------- fused: causal conv + silu + x_proj + dt_proj + softplus ---------
__global__ void __launch_bounds__(256) k_cxdt(int stage,
        const float* __restrict__ cw,  const float* __restrict__ cb,
        const float* __restrict__ xpw, const float* __restrict__ dpw,
        const float* __restrict__ dpb) {
    int lane = blockIdx.y;
    int blk  = 2 * stage + lane;
    int l0 = blockIdx.x * 32;
    int tid = threadIdx.x;

    __shared__ float xs[32][132];    // conv output tile
    __shared__ float wps[20][132];   // x_proj weights
    __shared__ float dps[128][4];    // dt_proj weights
    __shared__ float dpbs[128];
    __shared__ float dbc[32][24];

    const float* xcp = g_xcp[lane];

    for (int k = tid; k < 20 * 128; k += 256) {
        int e = k >> 7, d = k & 127;
        wps[e][d] = xpw[blk * 20 * DI + k];
    }
    if (tid < 128) {
        float4 v = *(const float4*)(dpw + blk * 512 + tid * 4);
        dps[tid][0] = v.x; dps[tid][1] = v.y; dps[tid][2] = v.z; dps[tid][3] = v.w;
        dpbs[tid] = dpb[blk * 128 + tid];
    }

    // conv + silu: 32 rows x 32 float4 groups
    for (int k = tid; k < 32 * 32; k += 256) {
        int r = k >> 5, d4 = k & 31;
        int lg = l0 + r;
        float4 wt0 = *(const float4*)(cw + (blk * 128 + d4 * 4 + 0) * 4);
        float4 wt1 = *(const float4*)(cw + (blk * 128 + d4 * 4 + 1) * 4);
        float4 wt2 = *(const float4*)(cw + (blk * 128 + d4 * 4 + 2) * 4);
        float4 wt3 = *(const float4*)(cw + (blk * 128 + d4 * 4 + 3) * 4);
        float4 b4  = *(const float4*)(cb + blk * 128 + d4 * 4);
        float4 x0 = *(const float4*)(xcp + lg * DI + d4 * 4);
        float4 x1 = (lg >= 1) ? *(const float4*)(xcp + (lg - 1) * DI + d4 * 4) : make_float4(0,0,0,0);
        float4 x2 = (lg >= 2) ? *(const float4*)(xcp + (lg - 2) * DI + d4 * 4) : make_float4(0,0,0,0);
        float4 x3 = (lg >= 3) ? *(const float4*)(xcp + (lg - 3) * DI + d4 * 4) : make_float4(0,0,0,0);
        float4 s;
        s.x = wt0.w * x0.x + wt0.z * x1.x + wt0.y * x2.x + wt0.x * x3.x + b4.x;
        s.y = wt1.w * x0.y + wt1.z * x1.y + wt1.y * x2.y + wt1.x * x3.y + b4.y;
        s.z = wt2.w * x0.z + wt2.z * x1.z + wt2.y * x2.z + wt2.x * x3.z + b4.z;
        s.w = wt3.w * x0.w + wt3.z * x1.w + wt3.y * x2.w + wt3.x * x3.w + b4.w;
        s.x = siluf(s.x); s.y = siluf(s.y); s.z = siluf(s.z); s.w = siluf(s.w);
        *(float4*)&xs[r][d4 * 4] = s;
        *(float4*)(g_xc[lane] + lg * DI + d4 * 4) = s;
    }
    __syncthreads();

    // phase A: dbc = xc @ xpw^T (per-thread full dot, no reductions)
    {
        int r = tid >> 3, g = tid & 7;
        int ne = (g < 4) ? 3 : 2;
        float accA[3] = {0.0f, 0.0f, 0.0f};
        #pragma unroll 4
        for (int d4 = 0; d4 < 32; d4++) {
            float4 xv = *(const float4*)&xs[r][d4 * 4];
            #pragma unroll
            for (int j = 0; j < 3; j++) {
                if (j < ne) {
                    int e = g + 8 * j;
                    float4 wv = *(const float4*)&wps[e][d4 * 4];
                    accA[j] += xv.x * wv.x + xv.y * wv.y + xv.z * wv.z + xv.w * wv.w;
                }
            }
        }
        #pragma unroll
        for (int j = 0; j < 3; j++)
            if (j < ne) dbc[r][g + 8 * j] = accA[j];
    }
    __syncthreads();

    // write B/C
    for (int k = tid; k < 32 * 16; k += 256) {
        int rr = k >> 4, s = k & 15;
        g_bc[lane][(l0 + rr) * 16 + s] = dbc[rr][4 + s];
    }
    // phase B: dt = softplus(dbc[:, :4] @ dpw^T + dpb)
    for (int k = tid; k < 32 * 128; k += 256) {
        int rr = k >> 7, d = k & 127;
        float x = dbc[rr][0] * dps[d][0] + dbc[rr][1] * dps[d][1]
                + dbc[rr][2] * dps[d][2] + dbc[rr][3] * dps[d][3] + dpbs[d];
        float sp = fmaxf(x, 0.0f) + __logf(1.0f + __expf(-fabsf(x)));
        g_dt[lane][(l0 + rr) * DI + d] = sp;
    }
}

// ------------------------- scan phase 1: per-chunk local scan --------------
__global__ void __launch_bounds__(128) k_scan1(int stage, const float* __restrict__ alog) {
    int lane = blockIdx.y;
    int blk  = 2 * stage + lane;
    int ch = blockIdx.x;
    int d  = threadIdx.x;
    int l0 = ch * CLEN;

    float a2[DS];
    #pragma unroll
    for (int s = 0; s < DS; s++)
        a2[s] = -1.4426950408889634f * __expf(alog[(blk * DI + d) * DS + s]);

    __shared__ float Bs[CLEN][DS];
    for (int k = d; k < CLEN * DS; k += 128) {
        int r = k >> 3, s = k & 7;
        Bs[r][s] = g_bc[lane][(l0 + r) * 16 + s];
    }
    __syncthreads();

    float h[DS], ap[DS];
    #pragma unroll
    for (int s = 0; s < DS; s++) { h[s] = 0.0f; ap[s] = 1.0f; }

    const float* dt = g_dt[lane];
    const float* xc = g_xc[lane];
    int base = l0 * DI + d;
    float dtv = dt[base], xcv = xc[base];
    for (int i = 0; i < CLEN; i++) {
        float dtn = 0.0f, xcn = 0.0f;
        if (i + 1 < CLEN) {
            dtn = dt[base + (i + 1) * DI];
            xcn = xc[base + (i + 1) * DI];
        }
        float w = dtv * xcv;
        #pragma unroll
        for (int s = 0; s < DS; s++) {
            float dA = exp2f(dtv * a2[s]);
            h[s]  = dA * h[s] + w * Bs[i][s];
            ap[s] *= dA;
        }
        dtv = dtn; xcv = xcn;
    }
    float2* out = g_aphl[lane] + ch * (DI * DS) + d * DS;
    #pragma unroll
    for (int s = 0; s < DS; s++) out[s] = make_float2(ap[s], h[s]);
}

// ------------------------- scan phase 2: pipelined chunk combine -----------
__global__ void __launch_bounds__(1024) k_scan2() {
    int lane = blockIdx.x;
    int t = threadIdx.x;
    const float2* aphl = g_aphl[lane];
    float* hin = g_hin[lane];
    float h = 0.0f;
    float2 buf[8];
    #pragma unroll
    for (int j = 0; j < 8; j++) buf[j] = aphl[j * 1024 + t];
    for (int c0 = 0; c0 < NCH; c0 += 8) {
        float2 nbuf[8];
        if (c0 + 8 < NCH) {
            #pragma unroll
            for (int j = 0; j < 8; j++) nbuf[j] = aphl[(c0 + 8 + j) * 1024 + t];
        } else {
            #pragma unroll
            for (int j = 0; j < 8; j++) nbuf[j] = make_float2(0.0f, 0.0f);
        }
        #pragma unroll
        for (int j = 0; j < 8; j++) {
            hin[(c0 + j) * 1024 + t] = h;
            h = buf[j].x * h + buf[j].y;
        }
        #pragma unroll
        for (int j = 0; j < 8; j++) buf[j] = nbuf[j];
    }
}

// ------------------------- scan phase 3: replay + output -------------------
__global__ void __launch_bounds__(128) k_scan3(int stage, const float* __restrict__ alog,
                                               const float* __restrict__ Dp) {
    int lane = blockIdx.y;
    int blk  = 2 * stage + lane;
    int ch = blockIdx.x;
    int d  = threadIdx.x;
    int l0 = ch * CLEN;

    float a2[DS];
    #pragma unroll
    for (int s = 0; s < DS; s++)
        a2[s] = -1.4426950408889634f * __expf(alog[(blk * DI + d) * DS + s]);
    float dpar = Dp[blk * DI + d];

    __shared__ float Bs[CLEN][DS];
    __shared__ float Cs[CLEN][DS];
    for (int k = d; k < CLEN * DS; k += 128) {
        int r = k >> 3, s = k & 7;
        Bs[r][s] = g_bc[lane][(l0 + r) * 16 + s];
        Cs[r][s] = g_bc[lane][(l0 + r) * 16 + 8 + s];
    }
    __syncthreads();

    float h[DS];
    const float* hind = g_hin[lane] + ch * (DI * DS) + d * DS;
    float4 h03 = *(const float4*)(hind);
    float4 h47 = *(const float4*)(hind + 4);
    h[0] = h03.x; h[1] = h03.y; h[2] = h03.z; h[3] = h03.w;
    h[4] = h47.x; h[5] = h47.y; h[6] = h47.z; h[7] = h47.w;

    const float* dt = g_dt[lane];
    const float* xc = g_xc[lane];
    const float* zz = g_z[lane];
    float* yz = g_yz[lane];
    int base = l0 * DI + d;
    float dtv = dt[base], xcv = xc[base], zv = zz[base];
    for (int i = 0; i < CLEN; i++) {
        float dtn = 0.0f, xcn = 0.0f, zn = 0.0f;
        if (i + 1 < CLEN) {
            dtn = dt[base + (i + 1) * DI];
            xcn = xc[base + (i + 1) * DI];
            zn  = zz[base + (i + 1) * DI];
        }
        float w = dtv * xcv;
        float y = dpar * xcv;
        #pragma unroll
        for (int s = 0; s < DS; s++) {
            float dA = exp2f(dtv * a2[s]);
            h[s] = dA * h[s] + w * Bs[i][s];
            y += h[s] * Cs[i][s];
        }
        yz[base + i * DI] = y * siluf(zv);
        dtv = dtn; xcv = xcn; zv = zn;
    }
}

// ------------- out_proj GEMM (FFMA2) + residual + scatter ------------------
__global__ void __launch_bounds__(256) k_outproj(int stage, int inb, int outb, int mode) {
    int lane = blockIdx.y;
    int blk  = 2 * stage + lane;
    __shared__ float ys_t[128][66];   // [d][r]
    int tid = threadIdx.x;
    int l0 = blockIdx.x * 64;
    const float* yz = g_yz[lane];
    for (int k = tid; k < 64 * 128; k += 256) {
        int r = k >> 7, d = k & 127;
        ys_t[d][r] = yz[(l0 + r) * DI + d];
    }
    __syncthreads();

    int og = tid & 15;        // 16 float4 col groups = 64 cols
    int rg = tid >> 4;        // 16 groups of 4 rows
    int r0 = rg * 4;
    const float4* wT = (const float4*)(g_wTout + blk * DI * DM);

    unsigned long long acc[4][2];
    #pragma unroll
    for (int q = 0; q < 4; q++) { acc[q][0] = 0ULL; acc[q][1] = 0ULL; }

    #pragma unroll 4
    for (int d = 0; d < 128; d++) {
        float4 w = wT[d * 16 + og];
        unsigned long long wx = pk2(w.x, w.x);
        unsigned long long wy = pk2(w.y, w.y);
        unsigned long long wz = pk2(w.z, w.z);
        unsigned long long ww = pk2(w.w, w.w);
        #pragma unroll
        for (int p = 0; p < 2; p++) {
            unsigned long long yp = *(const unsigned long long*)&ys_t[d][r0 + 2 * p];
            fma2(acc[0][p], wx, yp);
            fma2(acc[1][p], wy, yp);
            fma2(acc[2][p], wz, yp);
            fma2(acc[3][p], ww, yp);
        }
    }

    const float* curIn = curbuf(inb);
    float* curOut = curbuf(outb);
    int o0 = og * 4;
    #pragma unroll
    for (int p = 0; p < 2; p++) {
        float a0, a1, b0, b1, c0, c1, d0, d1;
        upk2(acc[0][p], a0, a1);
        upk2(acc[1][p], b0, b1);
        upk2(acc[2][p], c0, c1);
        upk2(acc[3][p], d0, d1);
        #pragma unroll
        for (int rr = 0; rr < 2; rr++) {
            int l = l0 + r0 + 2 * p + rr;
            int lt = lane ? (L - 1 - l) : l;
            int s = smap(lt, mode);
            int cc = lane * 64 + o0;
            float4 ri = *(const float4*)(curIn + s * C + cc);
            float4 ov;
            ov.x = (rr ? a1 : a0) + ri.x;
            ov.y = (rr ? b1 : b0) + ri.y;
            ov.z = (rr ? c1 : c0) + ri.z;
            ov.w = (rr ? d1 : d0) + ri.w;
            *(float4*)(curOut + s * C + cc) = ov;
        }
    }
}

// ---------------------------------------------------------------------------
extern "C" void kernel_launch(void* const* d_in, const int* in_sizes, int n_in,
                              void* d_out, int out_size) {
    (void)in_sizes; (void)n_in; (void)out_size;
    const float* x    = (const float*)d_in[0];
    const float* inw  = (const float*)d_in[1];
    const float* cw   = (const float*)d_in[2];
    const float* cb   = (const float*)d_in[3];
    const float* xpw  = (const float*)d_in[4];
    const float* dpw  = (const float*)d_in[5];
    const float* dpb  = (const float*)d_in[6];
    const float* alog = (const float*)d_in[7];
    const float* Dp   = (const float*)d_in[8];
    const float* opw  = (const float*)d_in[9];
    const float* lg   = (const float*)d_in[10];
    const float* lb   = (const float*)d_in[11];
    float* out = (float*)d_out;

    k_wt<<<384, 256>>>(inw, opw);
    k_tin<<<dim3(L / 32, C / 32), dim3(32, 32)>>>(x);

    for (int st = 0; st < 3; st++) {
        int inb  = (st == 1) ? 1 : 0;
        int outb = 1 - inb;
        int mode = st;
        k_ln<<<L, 128>>>(inb, lg + st * C, lb + st * C, mode);
        k_inproj<<<dim3(L / 32, 2), 256>>>(st);
        k_cxdt<<<dim3(L / 32, 2), 256>>>(st, cw, cb, xpw, dpw, dpb);
        k_scan1<<<dim3(NCH, 2), 128>>>(st, alog);
        k_scan2<<<2, 1024>>>();
        k_scan3<<<dim3(NCH, 2), 128>>>(st, alog, Dp);
        k_outproj<<<dim3(L / 64, 2), 256>>>(st, inb, outb, mode);
    }

    k_fin<<<dim3(L / 32, C / 32), dim3(32, 32)>>>(x, out);
}

// round 3
// speedup vs baseline: 1.3590x; 1.0421x over previous
#include <cuda_runtime.h>
#include <math.h>

// ---------------------------------------------------------------------------
// MambaLayer_image: 3 stages of bidirectional selective scan over 24^3 voxels.
// Fused pipeline: ln+inproj | conv+xproj+dtproj+scan1 | scan2 | scan3+outproj
// ---------------------------------------------------------------------------

namespace {
constexpr int L    = 13824;   // 24^3
constexpr int C    = 128;
constexpr int DM   = 64;
constexpr int DI   = 128;
constexpr int DS   = 8;
constexpr int CLEN = 32;       // scan chunk length (phase1/2 granularity)
constexpr int NCH  = L / CLEN; // 432
}

// ------------------------- device global scratch ---------------------------
__device__ __align__(16) float g_curA[L * C];
__device__ __align__(16) float g_curB[L * C];
__device__ __align__(16) float g_xcp[2][L * DI];
__device__ __align__(16) float g_z[2][L * DI];
__device__ __align__(16) float g_xc[2][L * DI];
__device__ __align__(16) float g_dt[2][L * DI];
__device__ __align__(16) float g_bc[2][L * 16];
__device__ __align__(16) float2 g_aphl[2][NCH * DI * DS];
__device__ __align__(16) float g_hin[2][NCH * DI * DS];
__device__ __align__(16) float g_wTin[6 * DM * 256];   // [blk][d][e]
__device__ __align__(16) float g_wTout[6 * DI * DM];   // [blk][d][o]

__device__ __forceinline__ float* curbuf(int i) { return i ? g_curB : g_curA; }

__device__ __forceinline__ int smap(int l, int mode) {
    if (mode == 0) return l;
    int a = l / 576;
    int r = l - a * 576;
    int b = r / 24;
    int c3 = r - b * 24;
    return (mode == 1) ? (c3 * 576 + a * 24 + b) : (b * 576 + c3 * 24 + a);
}

__device__ __forceinline__ float siluf(float x) {
    return x / (1.0f + __expf(-x));
}

// ---- packed f32x2 helpers --------------------------------------------------
__device__ __forceinline__ unsigned long long pk2(float lo, float hi) {
    unsigned long long r;
    asm("mov.b64 %0, {%1, %2};" : "=l"(r)
        : "r"(__float_as_uint(lo)), "r"(__float_as_uint(hi)));
    return r;
}
__device__ __forceinline__ void upk2(unsigned long long v, float& lo, float& hi) {
    unsigned int a, b;
    asm("mov.b64 {%0, %1}, %2;" : "=r"(a), "=r"(b) : "l"(v));
    lo = __uint_as_float(a); hi = __uint_as_float(b);
}
__device__ __forceinline__ void fma2(unsigned long long& d,
                                     unsigned long long a, unsigned long long b) {
    asm("fma.rn.f32x2 %0, %1, %2, %0;" : "+l"(d) : "l"(a), "l"(b));
}

// ------------------------- weight transposes -------------------------------
__global__ void k_wt(const float* __restrict__ inw, const float* __restrict__ opw) {
    int tid = blockIdx.x * 256 + threadIdx.x;
    if (tid < 6 * 256 * 64) {
        int b = tid / 16384;
        int r = tid - b * 16384;
        int e = r / 64;
        int d = r - e * 64;
        g_wTin[b * 16384 + d * 256 + e] = inw[tid];
    }
    if (tid < 6 * 64 * 128) {
        int b = tid / 8192;
        int r = tid - b * 8192;
        int o = r / 128;
        int d = r - o * 128;
        g_wTout[b * 8192 + d * 64 + o] = opw[tid];
    }
}

// ------------------------- input transpose (C,S) -> (S,C) ------------------
__global__ void k_tin(const float* __restrict__ x) {
    __shared__ float tile[32][33];
    int s0 = blockIdx.x * 32, c0 = blockIdx.y * 32;
    int tx = threadIdx.x, ty = threadIdx.y;
    tile[ty][tx] = x[(c0 + ty) * L + s0 + tx];
    __syncthreads();
    g_curA[(s0 + ty) * C + c0 + tx] = tile[tx][ty];
}

// ------------------------- final: out = cur^T + x --------------------------
__global__ void k_fin(const float* __restrict__ x, float* __restrict__ out) {
    __shared__ float tile[32][33];
    int s0 = blockIdx.x * 32, c0 = blockIdx.y * 32;
    int tx = threadIdx.x, ty = threadIdx.y;
    tile[ty][tx] = g_curB[(s0 + ty) * C + c0 + tx];
    __syncthreads();
    out[(c0 + ty) * L + s0 + tx] = tile[tx][ty] + x[(c0 + ty) * L + s0 + tx];
}

// ---------------- fused layernorm + in_proj (both lanes) -------------------
// block: 32 rows. LN in registers (8 threads/row), duplicated-pair tile in
// smem so the FFMA2 GEMM reads its broadcast operand with one LDS.64.
__global__ void __launch_bounds__(256) k_lnproj(int stage, int inb, int mode,
        const float* __restrict__ lg, const float* __restrict__ lb) {
    __shared__ float un2[32][260];   // duplicated: un2[r][2c] = un2[r][2c+1] = xn
    int tid = threadIdx.x;
    int l0 = blockIdx.x * 32;
    int row = tid >> 3;
    int seg = tid & 7;
    const float* cur = curbuf(inb);
    int l = l0 + row;
    int s = smap(l, mode);
    const float* rp = cur + s * C + seg * 16;
    float4 v0 = *(const float4*)(rp);
    float4 v1 = *(const float4*)(rp + 4);
    float4 v2 = *(const float4*)(rp + 8);
    float4 v3 = *(const float4*)(rp + 12);

    float sum = v0.x + v0.y + v0.z + v0.w + v1.x + v1.y + v1.z + v1.w
              + v2.x + v2.y + v2.z + v2.w + v3.x + v3.y + v3.z + v3.w;
    float sq  = v0.x*v0.x + v0.y*v0.y + v0.z*v0.z + v0.w*v0.w
              + v1.x*v1.x + v1.y*v1.y + v1.z*v1.z + v1.w*v1.w
              + v2.x*v2.x + v2.y*v2.y + v2.z*v2.z + v2.w*v2.w
              + v3.x*v3.x + v3.y*v3.y + v3.z*v3.z + v3.w*v3.w;
    #pragma unroll
    for (int o = 1; o < 8; o <<= 1) {
        sum += __shfl_xor_sync(0xffffffffu, sum, o);
        sq  += __shfl_xor_sync(0xffffffffu, sq,  o);
    }
    float m    = sum * (1.0f / 128.0f);
    float var  = sq * (1.0f / 128.0f) - m * m;
    float rstd = rsqrtf(var + 1e-5f);

    const float* lgp = lg + seg * 16;
    const float* lbp = lb + seg * 16;
    #pragma unroll
    for (int j = 0; j < 4; j++) {
        float4 v = (j == 0) ? v0 : (j == 1) ? v1 : (j == 2) ? v2 : v3;
        float4 g = __ldg((const float4*)(lgp + j * 4));
        float4 b = __ldg((const float4*)(lbp + j * 4));
        float nx = (v.x - m) * rstd * g.x + b.x;
        float ny = (v.y - m) * rstd * g.y + b.y;
        float nz = (v.z - m) * rstd * g.z + b.z;
        float nw = (v.w - m) * rstd * g.w + b.w;
        int c0 = seg * 16 + j * 4;
        *(float4*)&un2[row][2 * c0]     = make_float4(nx, nx, ny, ny);
        *(float4*)&un2[row][2 * c0 + 4] = make_float4(nz, nz, nw, nw);
    }
    __syncthreads();

    int e4 = tid & 63;        // 4 output cols: e0 = 4*e4
    int rg = tid >> 6;        // 4 groups of 8 rows
    int r0 = rg * 8;
    #pragma unroll
    for (int lane = 0; lane < 2; lane++) {
        int blk = 2 * stage + lane;
        const float4* wT = (const float4*)(g_wTin + blk * (DM * 256));
        unsigned long long acc[2][8];
        #pragma unroll
        for (int q = 0; q < 2; q++)
            #pragma unroll
            for (int r = 0; r < 8; r++) acc[q][r] = 0ULL;

        #pragma unroll 4
        for (int d = 0; d < 64; d++) {
            float4 w = __ldg(wT + d * 64 + e4);
            unsigned long long w01 = pk2(w.x, w.y);
            unsigned long long w23 = pk2(w.z, w.w);
            int cc = 2 * (lane * 64 + d);
            #pragma unroll
            for (int r = 0; r < 8; r++) {
                unsigned long long ub = *(const unsigned long long*)&un2[r0 + r][cc];
                fma2(acc[0][r], w01, ub);
                fma2(acc[1][r], w23, ub);
            }
        }
        int e0 = e4 * 4;
        float* dst;
        int off;
        if (e0 < 128) { dst = g_xcp[lane]; off = e0; }
        else          { dst = g_z[lane];   off = e0 - 128; }
        #pragma unroll
        for (int r = 0; r < 8; r++) {
            float a0, a1, b0, b1;
            upk2(acc[0][r], a0, a1);
            upk2(acc[1][r], b0, b1);
            int lrow = l0 + r0 + r;
            int ldst = lane ? (L - 1 - lrow) : lrow;
            *(float4*)(dst + ldst * DI + off) = make_float4(a0, a1, b0, b1);
        }
    }
}

// ---- fused: conv + silu + x_proj + dt_proj + softplus + scan phase 1 ------
__global__ void __launch_bounds__(256) k_cxs1(int stage,
        const float* __restrict__ cw,  const float* __restrict__ cb,
        const float* __restrict__ xpw, const float* __restrict__ dpw,
        const float* __restrict__ dpb, const float* __restrict__ alog) {
    int lane = blockIdx.y;
    int blk  = 2 * stage + lane;
    int l0 = blockIdx.x * CLEN;       // 32-row tile == scan chunk
    int tid = threadIdx.x;

    __shared__ float xs[32][132];     // conv+silu output
    __shared__ float wdt[32][132];    // x_proj weights (rows 0..19), then dt tile
    __shared__ float dbc[32][24];
    __shared__ float dps[128][4];
    __shared__ float dpbs[128];

    const float* xcp = g_xcp[lane];

    for (int k = tid; k < 20 * 128; k += 256) {
        int e = k >> 7, d = k & 127;
        wdt[e][d] = __ldg(xpw + blk * 20 * DI + k);
    }
    if (tid < 128) {
        float4 v = __ldg((const float4*)(dpw + blk * 512 + tid * 4));
        dps[tid][0] = v.x; dps[tid][1] = v.y; dps[tid][2] = v.z; dps[tid][3] = v.w;
        dpbs[tid] = __ldg(dpb + blk * 128 + tid);
    }

    // conv + silu
    for (int k = tid; k < 32 * 32; k += 256) {
        int r = k >> 5, d4 = k & 31;
        int lg = l0 + r;
        float4 wt0 = __ldg((const float4*)(cw + (blk * 128 + d4 * 4 + 0) * 4));
        float4 wt1 = __ldg((const float4*)(cw + (blk * 128 + d4 * 4 + 1) * 4));
        float4 wt2 = __ldg((const float4*)(cw + (blk * 128 + d4 * 4 + 2) * 4));
        float4 wt3 = __ldg((const float4*)(cw + (blk * 128 + d4 * 4 + 3) * 4));
        float4 b4  = __ldg((const float4*)(cb + blk * 128 + d4 * 4));
        float4 x0 = *(const float4*)(xcp + lg * DI + d4 * 4);
        float4 x1 = (lg >= 1) ? *(const float4*)(xcp + (lg - 1) * DI + d4 * 4) : make_float4(0,0,0,0);
        float4 x2 = (lg >= 2) ? *(const float4*)(xcp + (lg - 2) * DI + d4 * 4) : make_float4(0,0,0,0);
        float4 x3 = (lg >= 3) ? *(const float4*)(xcp + (lg - 3) * DI + d4 * 4) : make_float4(0,0,0,0);
        float4 sv;
        sv.x = wt0.w * x0.x + wt0.z * x1.x + wt0.y * x2.x + wt0.x * x3.x + b4.x;
        sv.y = wt1.w * x0.y + wt1.z * x1.y + wt1.y * x2.y + wt1.x * x3.y + b4.y;
        sv.z = wt2.w * x0.z + wt2.z * x1.z + wt2.y * x2.z + wt2.x * x3.z + b4.z;
        sv.w = wt3.w * x0.w + wt3.z * x1.w + wt3.y * x2.w + wt3.x * x3.w + b4.w;
        sv.x = siluf(sv.x); sv.y = siluf(sv.y); sv.z = siluf(sv.z); sv.w = siluf(sv.w);
        *(float4*)&xs[r][d4 * 4] = sv;
        *(float4*)(g_xc[lane] + lg * DI + d4 * 4) = sv;
    }
    __syncthreads();

    // phase A: dbc = xc @ xpw^T
    {
        int r = tid >> 3, g = tid & 7;
        int ne = (g < 4) ? 3 : 2;
        float accA[3] = {0.0f, 0.0f, 0.0f};
        #pragma unroll 4
        for (int d4 = 0; d4 < 32; d4++) {
            float4 xv = *(const float4*)&xs[r][d4 * 4];
            #pragma unroll
            for (int j = 0; j < 3; j++) {
                if (j < ne) {
                    int e = g + 8 * j;
                    float4 wv = *(const float4*)&wdt[e][d4 * 4];
                    accA[j] += xv.x * wv.x + xv.y * wv.y + xv.z * wv.z + xv.w * wv.w;
                }
            }
        }
        #pragma unroll
        for (int j = 0; j < 3; j++)
            if (j < ne) dbc[r][g + 8 * j] = accA[j];
    }
    __syncthreads();

    // write B/C
    for (int k = tid; k < 32 * 16; k += 256) {
        int rr = k >> 4, s = k & 15;
        g_bc[lane][(l0 + rr) * 16 + s] = dbc[rr][4 + s];
    }
    // phase B: dt = softplus(dbc[:, :4] @ dpw^T + dpb) -> global + smem (wdt)
    for (int k = tid; k < 32 * 128; k += 256) {
        int rr = k >> 7, d = k & 127;
        float x = dbc[rr][0] * dps[d][0] + dbc[rr][1] * dps[d][1]
                + dbc[rr][2] * dps[d][2] + dbc[rr][3] * dps[d][3] + dpbs[d];
        float sp = fmaxf(x, 0.0f) + __logf(1.0f + __expf(-fabsf(x)));
        g_dt[lane][(l0 + rr) * DI + d] = sp;
        wdt[rr][d] = sp;
    }
    __syncthreads();

    // scan phase 1 (local chunk scan) on threads 0..127
    if (tid < 128) {
        int d = tid;
        float a2[DS];
        #pragma unroll
        for (int s = 0; s < DS; s++)
            a2[s] = -1.4426950408889634f * __expf(__ldg(alog + (blk * DI + d) * DS + s));

        float h[DS], ap[DS];
        #pragma unroll
        for (int s = 0; s < DS; s++) { h[s] = 0.0f; ap[s] = 1.0f; }

        for (int i = 0; i < CLEN; i++) {
            float dtv = wdt[i][d];
            float xcv = xs[i][d];
            float4 Ba = *(const float4*)&dbc[i][4];
            float4 Bb = *(const float4*)&dbc[i][8];
            float Bv[DS] = {Ba.x, Ba.y, Ba.z, Ba.w, Bb.x, Bb.y, Bb.z, Bb.w};
            float w = dtv * xcv;
            #pragma unroll
            for (int s = 0; s < DS; s++) {
                float dA = exp2f(dtv * a2[s]);
                h[s]  = dA * h[s] + w * Bv[s];
                ap[s] *= dA;
            }
        }
        float2* out = g_aphl[lane] + blockIdx.x * (DI * DS) + d * DS;
        #pragma unroll
        for (int s = 0; s < DS; s++) out[s] = make_float2(ap[s], h[s]);
    }
}

// ------------------------- scan phase 2: pipelined chunk combine -----------
__global__ void __launch_bounds__(1024) k_scan2() {
    int lane = blockIdx.x;
    int t = threadIdx.x;
    const float2* aphl = g_aphl[lane];
    float* hin = g_hin[lane];
    float h = 0.0f;
    float2 buf[8];
    #pragma unroll
    for (int j = 0; j < 8; j++) buf[j] = aphl[j * 1024 + t];
    for (int c0 = 0; c0 < NCH; c0 += 8) {
        float2 nbuf[8];
        if (c0 + 8 < NCH) {
            #pragma unroll
            for (int j = 0; j < 8; j++) nbuf[j] = aphl[(c0 + 8 + j) * 1024 + t];
        } else {
            #pragma unroll
            for (int j = 0; j < 8; j++) nbuf[j] = make_float2(0.0f, 0.0f);
        }
        #pragma unroll
        for (int j = 0; j < 8; j++) {
            hin[(c0 + j) * 1024 + t] = h;
            h = buf[j].x * h + buf[j].y;
        }
        #pragma unroll
        for (int j = 0; j < 8; j++) buf[j] = nbuf[j];
    }
}

// ------- fused: scan phase 3 + out_proj (FFMA2) + residual + scatter -------
__global__ void __launch_bounds__(256) k_s3op(int stage, int inb, int outb, int mode,
        const float* __restrict__ alog, const float* __restrict__ Dp) {
    int lane = blockIdx.y;
    int blk  = 2 * stage + lane;
    int ch = blockIdx.x;
    int l0 = ch * 64;               // 64-row chunk = 2 phase-1 chunks
    int tid = threadIdx.x;

    __shared__ float ys_t[128][66];  // [d][row]
    __shared__ float Bs[64][8];
    __shared__ float Cs[64][8];

    for (int k = tid; k < 64 * 16; k += 256) {
        int r = k >> 4, s = k & 15;
        float v = g_bc[lane][(l0 + r) * 16 + s];
        if (s < 8) Bs[r][s] = v;
        else       Cs[r][s - 8] = v;
    }
    __syncthreads();

    if (tid < 128) {
        int d = tid;
        float a2[DS];
        #pragma unroll
        for (int s = 0; s < DS; s++)
            a2[s] = -1.4426950408889634f * __expf(__ldg(alog + (blk * DI + d) * DS + s));
        float dpar = __ldg(Dp + blk * DI + d);

        float h[DS];
        const float* hind = g_hin[lane] + (2 * ch) * (DI * DS) + d * DS;
        float4 h03 = *(const float4*)(hind);
        float4 h47 = *(const float4*)(hind + 4);
        h[0] = h03.x; h[1] = h03.y; h[2] = h03.z; h[3] = h03.w;
        h[4] = h47.x; h[5] = h47.y; h[6] = h47.z; h[7] = h47.w;

        const float* dt = g_dt[lane];
        const float* xc = g_xc[lane];
        const float* zz = g_z[lane];
        int base = l0 * DI + d;
        float dtv = dt[base], xcv = xc[base], zv = zz[base];
        for (int i = 0; i < 64; i++) {
            float dtn = 0.0f, xcn = 0.0f, zn = 0.0f;
            if (i + 1 < 64) {
                dtn = dt[base + (i + 1) * DI];
                xcn = xc[base + (i + 1) * DI];
                zn  = zz[base + (i + 1) * DI];
            }
            float w = dtv * xcv;
            float y = dpar * xcv;
            #pragma unroll
            for (int s = 0; s < DS; s++) {
                float dA = exp2f(dtv * a2[s]);
                h[s] = dA * h[s] + w * Bs[i][s];
                y += h[s] * Cs[i][s];
            }
            ys_t[d][i] = y * siluf(zv);
            dtv = dtn; xcv = xcn; zv = zn;
        }
    }
    __syncthreads();

    // out_proj GEMM 64x64x128 + residual + scatter
    int og = tid & 15;        // 16 float4 col groups = 64 cols
    int rg = tid >> 4;        // 16 groups of 4 rows
    int r0 = rg * 4;
    const float4* wT = (const float4*)(g_wTout + blk * DI * DM);

    unsigned long long acc[4][2];
    #pragma unroll
    for (int q = 0; q < 4; q++) { acc[q][0] = 0ULL; acc[q][1] = 0ULL; }

    #pragma unroll 4
    for (int d = 0; d < 128; d++) {
        float4 w = __ldg(wT + d * 16 + og);
        unsigned long long wx = pk2(w.x, w.x);
        unsigned long long wy = pk2(w.y, w.y);
        unsigned long long wz = pk2(w.z, w.w);  // placeholder fixed below
        wz = pk2(w.z, w.z);
        unsigned long long ww = pk2(w.w, w.w);
        #pragma unroll
        for (int p = 0; p < 2; p++) {
            unsigned long long yp = *(const unsigned long long*)&ys_t[d][r0 + 2 * p];
            fma2(acc[0][p], wx, yp);
            fma2(acc[1][p], wy, yp);
            fma2(acc[2][p], wz, yp);
            fma2(acc[3][p], ww, yp);
        }
    }

    const float* curIn = curbuf(inb);
    float* curOut = curbuf(outb);
    int o0 = og * 4;
    #pragma unroll
    for (int p = 0; p < 2; p++) {
        float a0, a1, b0, b1, c0, c1, d0, d1;
        upk2(acc[0][p], a0, a1);
        upk2(acc[1][p], b0, b1);
        upk2(acc[2][p], c0, c1);
        upk2(acc[3][p], d0, d1);
        #pragma unroll
        for (int rr = 0; rr < 2; rr++) {
            int l = l0 + r0 + 2 * p + rr;
            int lt = lane ? (L - 1 - l) : l;
            int s = smap(lt, mode);
            int cc = lane * 64 + o0;
            float4 ri = *(const float4*)(curIn + s * C + cc);
            float4 ov;
            ov.x = (rr ? a1 : a0) + ri.x;
            ov.y = (rr ? b1 : b0) + ri.y;
            ov.z = (rr ? c1 : c0) + ri.z;
            ov.w = (rr ? d1 : d0) + ri.w;
            *(float4*)(curOut + s * C + cc) = ov;
        }
    }
}

// ---------------------------------------------------------------------------
extern "C" void kernel_launch(void* const* d_in, const int* in_sizes, int n_in,
                              void* d_out, int out_size) {
    (void)in_sizes; (void)n_in; (void)out_size;
    const float* x    = (const float*)d_in[0];
    const float* inw  = (const float*)d_in[1];
    const float* cw   = (const float*)d_in[2];
    const float* cb   = (const float*)d_in[3];
    const float* xpw  = (const float*)d_in[4];
    const float* dpw  = (const float*)d_in[5];
    const float* dpb  = (const float*)d_in[6];
    const float* alog = (const float*)d_in[7];
    const float* Dp   = (const float*)d_in[8];
    const float* opw  = (const float*)d_in[9];
    const float* lg   = (const float*)d_in[10];
    const float* lb   = (const float*)d_in[11];
    float* out = (float*)d_out;

    k_wt<<<384, 256>>>(inw, opw);
    k_tin<<<dim3(L / 32, C / 32), dim3(32, 32)>>>(x);

    for (int st = 0; st < 3; st++) {
        int inb  = (st == 1) ? 1 : 0;
        int outb = 1 - inb;
        int mode = st;
        k_lnproj<<<L / 32, 256>>>(st, inb, mode, lg + st * C, lb + st * C);
        k_cxs1<<<dim3(NCH, 2), 256>>>(st, cw, cb, xpw, dpw, dpb, alog);
        k_scan2<<<2, 1024>>>();
        k_s3op<<<dim3(L / 64, 2), 256>>>(st, inb, outb, mode, alog, Dp);
    }

    k_fin<<<dim3(L / 32, C / 32), dim3(32, 32)>>>(x, out);
}

// round 4
// speedup vs baseline: 1.4039x; 1.0330x over previous
#include <cuda_runtime.h>
#include <math.h>

// ---------------------------------------------------------------------------
// MambaLayer_image: 3 stages of bidirectional selective scan over 24^3 voxels.
// Per stage: K1 = layernorm + in_proj (both lanes).
//            K2 = conv+silu + x_proj + single-pass selective scan with
//                 decoupled lookback + out_proj + residual scatter.
// ---------------------------------------------------------------------------

namespace {
constexpr int L    = 13824;   // 24^3
constexpr int C    = 128;
constexpr int DM   = 64;
constexpr int DI   = 128;
constexpr int DS   = 8;
constexpr int CLEN = 32;
constexpr int NCH  = L / CLEN; // 432
}

// ------------------------- device global scratch ---------------------------
__device__ __align__(16) float g_curA[L * C];
__device__ __align__(16) float g_curB[L * C];
__device__ __align__(16) float g_xcp[2][L * DI];
__device__ __align__(16) float g_z[2][L * DI];
__device__ __align__(16) float g_agg[2][NCH * 2048];   // per chunk: 1024 x (ap, h)
__device__ __align__(16) float g_incl[2][NCH * 1024];  // per chunk: 1024 inclusive h
__device__ int g_flag[2][NCH];
__device__ int g_tick[2];
__device__ __align__(16) float g_wTin[6 * DM * 256];   // [blk][d][e]
__device__ __align__(16) float g_wTout[6 * DI * DM];   // [blk][d][o]

__device__ __forceinline__ float* curbuf(int i) { return i ? g_curB : g_curA; }

__device__ __forceinline__ int smap(int l, int mode) {
    if (mode == 0) return l;
    int a = l / 576;
    int r = l - a * 576;
    int b = r / 24;
    int c3 = r - b * 24;
    return (mode == 1) ? (c3 * 576 + a * 24 + b) : (b * 576 + c3 * 24 + a);
}

__device__ __forceinline__ float siluf(float x) {
    return x / (1.0f + __expf(-x));
}

// ---- packed f32x2 helpers --------------------------------------------------
__device__ __forceinline__ unsigned long long pk2(float lo, float hi) {
    unsigned long long r;
    asm("mov.b64 %0, {%1, %2};" : "=l"(r)
        : "r"(__float_as_uint(lo)), "r"(__float_as_uint(hi)));
    return r;
}
__device__ __forceinline__ void upk2(unsigned long long v, float& lo, float& hi) {
    unsigned int a, b;
    asm("mov.b64 {%0, %1}, %2;" : "=r"(a), "=r"(b) : "l"(v));
    lo = __uint_as_float(a); hi = __uint_as_float(b);
}
__device__ __forceinline__ void fma2(unsigned long long& d,
                                     unsigned long long a, unsigned long long b) {
    asm("fma.rn.f32x2 %0, %1, %2, %0;" : "+l"(d) : "l"(a), "l"(b));
}

// ---- acquire/release flag ops ---------------------------------------------
__device__ __forceinline__ int ld_acq(const int* p) {
    int v;
    asm volatile("ld.acquire.gpu.b32 %0, [%1];" : "=r"(v) : "l"(p) : "memory");
    return v;
}
__device__ __forceinline__ void st_rel(int* p, int v) {
    asm volatile("st.release.gpu.b32 [%0], %1;" :: "l"(p), "r"(v) : "memory");
}

// ------------------------- weight transposes -------------------------------
__global__ void k_wt(const float* __restrict__ inw, const float* __restrict__ opw) {
    int tid = blockIdx.x * 256 + threadIdx.x;
    if (tid < 6 * 256 * 64) {
        int b = tid / 16384;
        int r = tid - b * 16384;
        int e = r / 64;
        int d = r - e * 64;
        g_wTin[b * 16384 + d * 256 + e] = inw[tid];
    }
    if (tid < 6 * 64 * 128) {
        int b = tid / 8192;
        int r = tid - b * 8192;
        int o = r / 128;
        int d = r - o * 128;
        g_wTout[b * 8192 + d * 64 + o] = opw[tid];
    }
}

// ------------------------- input transpose (C,S) -> (S,C) ------------------
__global__ void k_tin(const float* __restrict__ x) {
    __shared__ float tile[32][33];
    int s0 = blockIdx.x * 32, c0 = blockIdx.y * 32;
    int tx = threadIdx.x, ty = threadIdx.y;
    tile[ty][tx] = x[(c0 + ty) * L + s0 + tx];
    __syncthreads();
    g_curA[(s0 + ty) * C + c0 + tx] = tile[tx][ty];
}

// ------------------------- final: out = cur^T + x --------------------------
__global__ void k_fin(const float* __restrict__ x, float* __restrict__ out) {
    __shared__ float tile[32][33];
    int s0 = blockIdx.x * 32, c0 = blockIdx.y * 32;
    int tx = threadIdx.x, ty = threadIdx.y;
    tile[ty][tx] = g_curB[(s0 + ty) * C + c0 + tx];
    __syncthreads();
    out[(c0 + ty) * L + s0 + tx] = tile[tx][ty] + x[(c0 + ty) * L + s0 + tx];
}

// ---------------- K1: fused layernorm + in_proj (both lanes) ---------------
__global__ void __launch_bounds__(256) k_lnproj(int stage, int inb, int mode,
        const float* __restrict__ lg, const float* __restrict__ lb) {
    // block 0 also resets lookback state for the following k_mega
    if (blockIdx.x == 0) {
        int t = threadIdx.x;
        for (int i = t; i < 2 * NCH; i += 256) ((int*)g_flag)[i] = 0;
        if (t < 2) g_tick[t] = 0;
    }

    __shared__ float un2[32][260];   // duplicated pairs: un2[r][2c]=un2[r][2c+1]
    int tid = threadIdx.x;
    int l0 = blockIdx.x * 32;
    int row = tid >> 3;
    int seg = tid & 7;
    const float* cur = curbuf(inb);
    int l = l0 + row;
    int s = smap(l, mode);
    const float* rp = cur + s * C + seg * 16;
    float4 v0 = *(const float4*)(rp);
    float4 v1 = *(const float4*)(rp + 4);
    float4 v2 = *(const float4*)(rp + 8);
    float4 v3 = *(const float4*)(rp + 12);

    float sum = v0.x + v0.y + v0.z + v0.w + v1.x + v1.y + v1.z + v1.w
              + v2.x + v2.y + v2.z + v2.w + v3.x + v3.y + v3.z + v3.w;
    float sq  = v0.x*v0.x + v0.y*v0.y + v0.z*v0.z + v0.w*v0.w
              + v1.x*v1.x + v1.y*v1.y + v1.z*v1.z + v1.w*v1.w
              + v2.x*v2.x + v2.y*v2.y + v2.z*v2.z + v2.w*v2.w
              + v3.x*v3.x + v3.y*v3.y + v3.z*v3.z + v3.w*v3.w;
    #pragma unroll
    for (int o = 1; o < 8; o <<= 1) {
        sum += __shfl_xor_sync(0xffffffffu, sum, o);
        sq  += __shfl_xor_sync(0xffffffffu, sq,  o);
    }
    float m    = sum * (1.0f / 128.0f);
    float var  = sq * (1.0f / 128.0f) - m * m;
    float rstd = rsqrtf(var + 1e-5f);

    const float* lgp = lg + seg * 16;
    const float* lbp = lb + seg * 16;
    #pragma unroll
    for (int j = 0; j < 4; j++) {
        float4 v = (j == 0) ? v0 : (j == 1) ? v1 : (j == 2) ? v2 : v3;
        float4 g = __ldg((const float4*)(lgp + j * 4));
        float4 b = __ldg((const float4*)(lbp + j * 4));
        float nx = (v.x - m) * rstd * g.x + b.x;
        float ny = (v.y - m) * rstd * g.y + b.y;
        float nz = (v.z - m) * rstd * g.z + b.z;
        float nw = (v.w - m) * rstd * g.w + b.w;
        int c0 = seg * 16 + j * 4;
        *(float4*)&un2[row][2 * c0]     = make_float4(nx, nx, ny, ny);
        *(float4*)&un2[row][2 * c0 + 4] = make_float4(nz, nz, nw, nw);
    }
    __syncthreads();

    int e4 = tid & 63;
    int rg = tid >> 6;
    int r0 = rg * 8;
    #pragma unroll
    for (int lane = 0; lane < 2; lane++) {
        int blk = 2 * stage + lane;
        const float4* wT = (const float4*)(g_wTin + blk * (DM * 256));
        unsigned long long acc[2][8];
        #pragma unroll
        for (int q = 0; q < 2; q++)
            #pragma unroll
            for (int r = 0; r < 8; r++) acc[q][r] = 0ULL;

        #pragma unroll 4
        for (int d = 0; d < 64; d++) {
            float4 w = __ldg(wT + d * 64 + e4);
            unsigned long long w01 = pk2(w.x, w.y);
            unsigned long long w23 = pk2(w.z, w.w);
            int cc = 2 * (lane * 64 + d);
            #pragma unroll
            for (int r = 0; r < 8; r++) {
                unsigned long long ub = *(const unsigned long long*)&un2[r0 + r][cc];
                fma2(acc[0][r], w01, ub);
                fma2(acc[1][r], w23, ub);
            }
        }
        int e0 = e4 * 4;
        float* dst;
        int off;
        if (e0 < 128) { dst = g_xcp[lane]; off = e0; }
        else          { dst = g_z[lane];   off = e0 - 128; }
        #pragma unroll
        for (int r = 0; r < 8; r++) {
            float a0, a1, b0, b1;
            upk2(acc[0][r], a0, a1);
            upk2(acc[1][r], b0, b1);
            int lrow = l0 + r0 + r;
            int ldst = lane ? (L - 1 - lrow) : lrow;
            *(float4*)(dst + ldst * DI + off) = make_float4(a0, a1, b0, b1);
        }
    }
}

// ---------------- K2: conv + x_proj + one-pass scan + out_proj -------------
__global__ void __launch_bounds__(256) k_mega(int stage, int inb, int outb, int mode,
        const float* __restrict__ cw,  const float* __restrict__ cb,
        const float* __restrict__ xpw, const float* __restrict__ dpw,
        const float* __restrict__ dpb, const float* __restrict__ alog,
        const float* __restrict__ Dp) {
    int lane = blockIdx.y;
    int blk  = 2 * stage + lane;
    int tid  = threadIdx.x;

    __shared__ float R[4352];          // union: wps[20][132] -> ys_t[128][34]
    __shared__ float xs[32][132];
    __shared__ float dbc[32][24];
    __shared__ float dps4[128][4];
    __shared__ float dpbs[128];
    __shared__ int s_chunk, s_q;

    float (*wps)[132] = (float(*)[132])R;
    float (*ys_t)[34] = (float(*)[34])R;

    if (tid == 0) s_chunk = atomicAdd(&g_tick[lane], 1);

    // load x_proj / dt_proj weights
    for (int k = tid; k < 20 * 128; k += 256) {
        int e = k >> 7, d = k & 127;
        wps[e][d] = __ldg(xpw + blk * 20 * DI + k);
    }
    if (tid < 128) {
        float4 v = __ldg((const float4*)(dpw + blk * 512 + tid * 4));
        dps4[tid][0] = v.x; dps4[tid][1] = v.y; dps4[tid][2] = v.z; dps4[tid][3] = v.w;
        dpbs[tid] = __ldg(dpb + blk * 128 + tid);
    }
    __syncthreads();
    int c  = s_chunk;
    int l0 = c * CLEN;

    // conv + silu -> xs
    const float* xcp = g_xcp[lane];
    for (int k = tid; k < 32 * 32; k += 256) {
        int r = k >> 5, d4 = k & 31;
        int lg = l0 + r;
        float4 wt0 = __ldg((const float4*)(cw + (blk * 128 + d4 * 4 + 0) * 4));
        float4 wt1 = __ldg((const float4*)(cw + (blk * 128 + d4 * 4 + 1) * 4));
        float4 wt2 = __ldg((const float4*)(cw + (blk * 128 + d4 * 4 + 2) * 4));
        float4 wt3 = __ldg((const float4*)(cw + (blk * 128 + d4 * 4 + 3) * 4));
        float4 b4  = __ldg((const float4*)(cb + blk * 128 + d4 * 4));
        float4 x0 = *(const float4*)(xcp + lg * DI + d4 * 4);
        float4 x1 = (lg >= 1) ? *(const float4*)(xcp + (lg - 1) * DI + d4 * 4) : make_float4(0,0,0,0);
        float4 x2 = (lg >= 2) ? *(const float4*)(xcp + (lg - 2) * DI + d4 * 4) : make_float4(0,0,0,0);
        float4 x3 = (lg >= 3) ? *(const float4*)(xcp + (lg - 3) * DI + d4 * 4) : make_float4(0,0,0,0);
        float4 sv;
        sv.x = wt0.w * x0.x + wt0.z * x1.x + wt0.y * x2.x + wt0.x * x3.x + b4.x;
        sv.y = wt1.w * x0.y + wt1.z * x1.y + wt1.y * x2.y + wt1.x * x3.y + b4.y;
        sv.z = wt2.w * x0.z + wt2.z * x1.z + wt2.y * x2.z + wt2.x * x3.z + b4.z;
        sv.w = wt3.w * x0.w + wt3.z * x1.w + wt3.y * x2.w + wt3.x * x3.w + b4.w;
        sv.x = siluf(sv.x); sv.y = siluf(sv.y); sv.z = siluf(sv.z); sv.w = siluf(sv.w);
        *(float4*)&xs[r][d4 * 4] = sv;
    }
    __syncthreads();

    // x_proj: dbc = xs @ wps^T  (20 outputs per row)
    {
        int r = tid >> 3, g = tid & 7;
        int ne = (g < 4) ? 3 : 2;
        float accA[3] = {0.0f, 0.0f, 0.0f};
        #pragma unroll 4
        for (int d4 = 0; d4 < 32; d4++) {
            float4 xv = *(const float4*)&xs[r][d4 * 4];
            #pragma unroll
            for (int j = 0; j < 3; j++) {
                if (j < ne) {
                    int e = g + 8 * j;
                    float4 wv = *(const float4*)&wps[e][d4 * 4];
                    accA[j] += xv.x * wv.x + xv.y * wv.y + xv.z * wv.z + xv.w * wv.w;
                }
            }
        }
        #pragma unroll
        for (int j = 0; j < 3; j++)
            if (j < ne) dbc[r][g + 8 * j] = accA[j];
    }
    __syncthreads();   // wps dead; R becomes ys_t

    // ---- scan phase 1: 2 threads/channel, 4 states each -------------------
    int d   = tid >> 1;
    int sq4 = (tid & 1) * 4;
    float a2[4];
    {
        const float* ga = alog + (blk * DI + d) * DS + sq4;
        a2[0] = -1.4426950408889634f * __expf(__ldg(ga + 0));
        a2[1] = -1.4426950408889634f * __expf(__ldg(ga + 1));
        a2[2] = -1.4426950408889634f * __expf(__ldg(ga + 2));
        a2[3] = -1.4426950408889634f * __expf(__ldg(ga + 3));
    }
    float4 dwv = *(const float4*)dps4[d];
    float dbv  = dpbs[d];

    float ap0 = 1.f, ap1 = 1.f, ap2 = 1.f, ap3 = 1.f;
    float hl0 = 0.f, hl1 = 0.f, hl2 = 0.f, hl3 = 0.f;
    for (int i = 0; i < CLEN; i++) {
        float4 dtc = *(const float4*)&dbc[i][0];
        float xv = dtc.x * dwv.x + dtc.y * dwv.y + dtc.z * dwv.z + dtc.w * dwv.w + dbv;
        float dtv = fmaxf(xv, 0.f) + __logf(1.f + __expf(-fabsf(xv)));
        float w = dtv * xs[i][d];
        float4 Bv = *(const float4*)&dbc[i][4 + sq4];
        float dA0 = exp2f(dtv * a2[0]); hl0 = dA0 * hl0 + w * Bv.x; ap0 *= dA0;
        float dA1 = exp2f(dtv * a2[1]); hl1 = dA1 * hl1 + w * Bv.y; ap1 *= dA1;
        float dA2 = exp2f(dtv * a2[2]); hl2 = dA2 * hl2 + w * Bv.z; ap2 *= dA2;
        float dA3 = exp2f(dtv * a2[3]); hl3 = dA3 * hl3 + w * Bv.w; ap3 *= dA3;
    }

    float h00 = 0.f, h01 = 0.f, h02 = 0.f, h03 = 0.f;
    if (c > 0) {
        // publish aggregate
        float* ag = g_agg[lane] + (size_t)c * 2048 + tid * 8;
        *(float4*)ag       = make_float4(ap0, hl0, ap1, hl1);
        *(float4*)(ag + 4) = make_float4(ap2, hl2, ap3, hl3);
        __threadfence();
        __syncthreads();
        if (tid == 0) st_rel(&g_flag[lane][c], 1);

        // decoupled lookback
        float A0 = 1.f, A1 = 1.f, A2 = 1.f, A3 = 1.f;
        float H0 = 0.f, H1 = 0.f, H2 = 0.f, H3 = 0.f;
        int p = c - 1;
        for (;;) {
            int lo = p - 31; if (lo < 0) lo = 0;
            if (tid < 32) {
                int j = p - tid;
                bool act = (j >= lo);
                int f = 3;
                for (;;) {
                    if (act) f = ld_acq(&g_flag[lane][j]);
                    unsigned rdy = __ballot_sync(0xffffffffu, f >= 1);
                    if (rdy == 0xffffffffu) break;
                }
                unsigned has2 = __ballot_sync(0xffffffffu, act && (f == 2));
                if (tid == 0) s_q = has2 ? (p - (__ffs(has2) - 1)) : -1;
            }
            __syncthreads();
            int q = s_q;
            __syncthreads();
            int lo2 = (q >= 0) ? (q + 1) : lo;
            int j = p;
            while (j >= lo2) {
                int n = j - lo2 + 1; if (n > 4) n = 4;
                float4 pa[4], pb[4];
                #pragma unroll
                for (int k = 0; k < 4; k++) if (k < n) {
                    const float* ag2 = g_agg[lane] + (size_t)(j - k) * 2048 + tid * 8;
                    pa[k] = *(const float4*)ag2;
                    pb[k] = *(const float4*)(ag2 + 4);
                }
                #pragma unroll
                for (int k = 0; k < 4; k++) if (k < n) {
                    H0 += A0 * pa[k].y; A0 *= pa[k].x;
                    H1 += A1 * pa[k].w; A1 *= pa[k].z;
                    H2 += A2 * pb[k].y; A2 *= pb[k].x;
                    H3 += A3 * pb[k].w; A3 *= pb[k].z;
                }
                j -= n;
            }
            if (q >= 0) {
                float4 iv = *(const float4*)(g_incl[lane] + (size_t)q * 1024 + tid * 4);
                h00 = A0 * iv.x + H0;
                h01 = A1 * iv.y + H1;
                h02 = A2 * iv.z + H2;
                h03 = A3 * iv.w + H3;
                break;
            }
            p = lo - 1;
        }
    }

    // publish inclusive
    {
        float i0 = ap0 * h00 + hl0;
        float i1 = ap1 * h01 + hl1;
        float i2 = ap2 * h02 + hl2;
        float i3 = ap3 * h03 + hl3;
        *(float4*)(g_incl[lane] + (size_t)c * 1024 + tid * 4) = make_float4(i0, i1, i2, i3);
        __threadfence();
        __syncthreads();
        if (tid == 0) st_rel(&g_flag[lane][c], 2);
    }

    // ---- scan phase 3: replay from h0, emit ys ----------------------------
    {
        float dpar = __ldg(Dp + blk * DI + d);
        const float* zz = g_z[lane];
        float hh0 = h00, hh1 = h01, hh2 = h02, hh3 = h03;
        for (int i = 0; i < CLEN; i++) {
            float4 dtc = *(const float4*)&dbc[i][0];
            float xv = dtc.x * dwv.x + dtc.y * dwv.y + dtc.z * dwv.z + dtc.w * dwv.w + dbv;
            float dtv = fmaxf(xv, 0.f) + __logf(1.f + __expf(-fabsf(xv)));
            float xcv = xs[i][d];
            float w = dtv * xcv;
            float4 Bv = *(const float4*)&dbc[i][4 + sq4];
            float4 Cv = *(const float4*)&dbc[i][12 + sq4];
            float dA0 = exp2f(dtv * a2[0]); hh0 = dA0 * hh0 + w * Bv.x;
            float dA1 = exp2f(dtv * a2[1]); hh1 = dA1 * hh1 + w * Bv.y;
            float dA2 = exp2f(dtv * a2[2]); hh2 = dA2 * hh2 + w * Bv.z;
            float dA3 = exp2f(dtv * a2[3]); hh3 = dA3 * hh3 + w * Bv.w;
            float y = hh0 * Cv.x + hh1 * Cv.y + hh2 * Cv.z + hh3 * Cv.w;
            y += __shfl_xor_sync(0xffffffffu, y, 1);
            if ((tid & 1) == 0) {
                float zv = __ldg(zz + (l0 + i) * DI + d);
                ys_t[d][i] = (y + dpar * xcv) * siluf(zv);
            }
        }
    }
    __syncthreads();

    // ---- out_proj GEMM (32x64x128, FFMA2) + residual + scatter ------------
    {
        int og = tid & 15;
        int rg = tid >> 4;
        const float4* wT = (const float4*)(g_wTout + blk * DI * DM);
        unsigned long long a0 = 0ULL, a1 = 0ULL, a2u = 0ULL, a3 = 0ULL;
        #pragma unroll 4
        for (int dd = 0; dd < 128; dd++) {
            float4 w = __ldg(wT + dd * 16 + og);
            unsigned long long yp = *(const unsigned long long*)&ys_t[dd][rg * 2];
            fma2(a0, pk2(w.x, w.x), yp);
            fma2(a1, pk2(w.y, w.y), yp);
            fma2(a2u, pk2(w.z, w.z), yp);
            fma2(a3, pk2(w.w, w.w), yp);
        }
        const float* curIn = curbuf(inb);
        float* curOut = curbuf(outb);
        int o0 = og * 4;
        float x0, x1, y0, y1, z0, z1, w0, w1;
        upk2(a0, x0, x1);
        upk2(a1, y0, y1);
        upk2(a2u, z0, z1);
        upk2(a3, w0, w1);
        #pragma unroll
        for (int rr = 0; rr < 2; rr++) {
            int l = l0 + rg * 2 + rr;
            int lt = lane ? (L - 1 - l) : l;
            int s = smap(lt, mode);
            int cc = lane * 64 + o0;
            float4 ri = *(const float4*)(curIn + s * C + cc);
            float4 ov;
            ov.x = (rr ? x1 : x0) + ri.x;
            ov.y = (rr ? y1 : y0) + ri.y;
            ov.z = (rr ? z1 : z0) + ri.z;
            ov.w = (rr ? w1 : w0) + ri.w;
            *(float4*)(curOut + s * C + cc) = ov;
        }
    }
}

// ---------------------------------------------------------------------------
extern "C" void kernel_launch(void* const* d_in, const int* in_sizes, int n_in,
                              void* d_out, int out_size) {
    (void)in_sizes; (void)n_in; (void)out_size;
    const float* x    = (const float*)d_in[0];
    const float* inw  = (const float*)d_in[1];
    const float* cw   = (const float*)d_in[2];
    const float* cb   = (const float*)d_in[3];
    const float* xpw  = (const float*)d_in[4];
    const float* dpw  = (const float*)d_in[5];
    const float* dpb  = (const float*)d_in[6];
    const float* alog = (const float*)d_in[7];
    const float* Dp   = (const float*)d_in[8];
    const float* opw  = (const float*)d_in[9];
    const float* lg   = (const float*)d_in[10];
    const float* lb   = (const float*)d_in[11];
    float* out = (float*)d_out;

    k_wt<<<384, 256>>>(inw, opw);
    k_tin<<<dim3(L / 32, C / 32), dim3(32, 32)>>>(x);

    for (int st = 0; st < 3; st++) {
        int inb  = (st == 1) ? 1 : 0;
        int outb = 1 - inb;
        int mode = st;
        k_lnproj<<<L / 32, 256>>>(st, inb, mode, lg + st * C, lb + st * C);
        k_mega<<<dim3(NCH, 2), 256>>>(st, inb, outb, mode,
                                      cw, cb, xpw, dpw, dpb, alog, Dp);
    }

    k_fin<<<dim3(L / 32, C / 32), dim3(32, 32)>>>(x, out);
}